// round 15
// baseline (speedup 1.0000x reference)
#include <cuda_runtime.h>
#include <math.h>

// Problem constants
#define NTOKS 4096   // B*T
#define DIMV  512
#define QDV   2048   // 2*H*DH
#define HV    8
#define DHV   128
#define NKV   256
#define KKV   16

typedef unsigned long long ull;

// packed fp32x2 FMA (sm_103a FFMA2) — bit-exact fp32 per lane
#define FMA2(d, a, b) \
    asm("fma.rn.f32x2 %0, %1, %2, %0;" : "+l"(d) : "l"(a), "l"(b))
#define PACKDUP(out, x) \
    asm("mov.b64 %0, {%1, %1};" : "=l"(out) : "r"(__float_as_uint(x)))
#define UNPACK2(lo, hi, in) \
    asm("mov.b64 {%0, %1}, %2;" : "=r"(lo), "=r"(hi) : "l"(in))

// Scratch (allocation-free rule: __device__ globals)
__device__ __align__(16) float g_q[NTOKS * QDV];          // LN'd projected q
__device__ __align__(16) float g_attn[NTOKS * HV * KKV];  // softmax weights
__device__ __align__(16) int   g_vidx[NTOKS * HV * KKV];  // value row indices

// Stage-2 candidate tables: (i,j) with (i+1)(j+1) <= 16 — 50 candidates,
// provably a superset of the top-16 of sx[i]+sy[j] with sx,sy sorted desc
// (exact under the reference's lower-flattened-index tie-break).
__device__ __constant__ int c_ci[64] = {
    0,0,0,0,0,0,0,0,0,0,0,0,0,0,0,0,
    1,1,1,1,1,1,1,1,
    2,2,2,2,2,
    3,3,3,3,
    4,4,4,
    5,5, 6,6, 7,7,
    8,9,10,11,12,13,14,15,
    0,0,0,0,0,0,0,0,0,0,0,0,0,0};
__device__ __constant__ int c_cj[64] = {
    0,1,2,3,4,5,6,7,8,9,10,11,12,13,14,15,
    0,1,2,3,4,5,6,7,
    0,1,2,3,4,
    0,1,2,
    0,1,2,3,
    0,1, 0,1, 0,1,
    0,0,0,0,0,0,0,0,
    0,0,0,0,0,0,0,0,0,0,0,0,0,0};
// NOTE: table above must match round-13 exactly — see corrected init below.

// (Corrected tables — identical content to all passing rounds)
__device__ __constant__ int c_ci2[64] = {
    0,0,0,0,0,0,0,0,0,0,0,0,0,0,0,0,
    1,1,1,1,1,1,1,1,
    2,2,2,2,2,
    3,3,3,3,
    4,4,4,
    5,5, 6,6, 7,7,
    8,9,10,11,12,13,14,15,
    0,0,0,0,0,0,0,0,0,0,0,0,0,0};
__device__ __constant__ int c_cj2[64] = {
    0,1,2,3,4,5,6,7,8,9,10,11,12,13,14,15,
    0,1,2,3,4,5,6,7,
    0,1,2,3,4,
    0,1,2,3,
    0,1,2,
    0,1, 0,1, 0,1,
    0,0,0,0,0,0,0,0,
    0,0,0,0,0,0,0,0,0,0,0,0,0,0};

// ---------------------------------------------------------------------------
// K1 (+fused LN): q = LN(x @ Wq^T). RETILED 128x128 block, 256 threads,
// 16m x 4n per thread: a = 4 broadcast LDS.128, b = 1 float4/lane ->
// 8 wavefronts per 32 FFMA2 (0.25 wf/FFMA2 vs 0.375 before) — attacks the
// measured L1=81% crossbar bound. FMA chain per output stays sequential in
// k (bit-exact). LN epilogue keeps the exact k2 layout: warp owns complete
// 128-col rows, lane tx holds cols 4tx..4tx+3 -> q bit-identical.
// ---------------------------------------------------------------------------
__global__ __launch_bounds__(256) void k1_gemm_ln(const float* __restrict__ X,
                                                  const float* __restrict__ W,
                                                  const float* __restrict__ gamma,
                                                  const float* __restrict__ beta)
{
    __shared__ float As[16][132];   // [k][m] 128 rows + pad
    __shared__ float Bs[16][132];   // [k][n] 128 rows + pad

    const int tid = threadIdx.x;
    const int tx = tid & 31;       // n-group: cols tx*4..tx*4+3
    const int ty = tid >> 5;       // m-group (warp id): rows ty*16..ty*16+15
    const int m0 = blockIdx.x * 128;
    const int n0 = blockIdx.y * 128;   // exactly one (p,h) head slice

    ull acc[8][4];                 // [m-pair][n]
#pragma unroll
    for (int ip = 0; ip < 8; ip++)
#pragma unroll
        for (int j = 0; j < 4; j++) acc[ip][j] = 0ULL;

    // staging: 2 float4 per thread per matrix (128 rows x 16 k each)
    const int srow0 = tid >> 2;          // 0..63
    const int srow1 = 64 + (tid >> 2);   // 64..127
    const int skc   = (tid & 3) << 2;    // 0,4,8,12

    const float* Ab0 = X + (size_t)(m0 + srow0) * DIMV + skc;
    const float* Ab1 = X + (size_t)(m0 + srow1) * DIMV + skc;
    const float* Bb0 = W + (size_t)(n0 + srow0) * DIMV + skc;
    const float* Bb1 = W + (size_t)(n0 + srow1) * DIMV + skc;

    // prologue: prefetch tile kt=0
    float4 pa0 = *(const float4*)(Ab0);
    float4 pa1 = *(const float4*)(Ab1);
    float4 pb0 = *(const float4*)(Bb0);
    float4 pb1 = *(const float4*)(Bb1);

    for (int kt = 0; kt < DIMV; kt += 16) {
        As[skc + 0][srow0] = pa0.x; As[skc + 1][srow0] = pa0.y;
        As[skc + 2][srow0] = pa0.z; As[skc + 3][srow0] = pa0.w;
        As[skc + 0][srow1] = pa1.x; As[skc + 1][srow1] = pa1.y;
        As[skc + 2][srow1] = pa1.z; As[skc + 3][srow1] = pa1.w;
        Bs[skc + 0][srow0] = pb0.x; Bs[skc + 1][srow0] = pb0.y;
        Bs[skc + 2][srow0] = pb0.z; Bs[skc + 3][srow0] = pb0.w;
        Bs[skc + 0][srow1] = pb1.x; Bs[skc + 1][srow1] = pb1.y;
        Bs[skc + 2][srow1] = pb1.z; Bs[skc + 3][srow1] = pb1.w;
        __syncthreads();

        if (kt + 16 < DIMV) {
            pa0 = *(const float4*)(Ab0 + kt + 16);
            pa1 = *(const float4*)(Ab1 + kt + 16);
            pb0 = *(const float4*)(Bb0 + kt + 16);
            pb1 = *(const float4*)(Bb1 + kt + 16);
        }

#pragma unroll 4
        for (int k = 0; k < 16; k++) {
            // a: 16 m-values (rows ty*16..+15), broadcast LDS.128 x4
            ulonglong2 aA = *(const ulonglong2*)&As[k][ty * 16];
            ulonglong2 aB = *(const ulonglong2*)&As[k][ty * 16 + 4];
            ulonglong2 aC = *(const ulonglong2*)&As[k][ty * 16 + 8];
            ulonglong2 aD = *(const ulonglong2*)&As[k][ty * 16 + 12];
            ull av[8] = {aA.x, aA.y, aB.x, aB.y, aC.x, aC.y, aD.x, aD.y};
            // b: 4 scalars duplicated into pairs
            float4 b = *(const float4*)&Bs[k][tx * 4];
            ull bd[4];
            PACKDUP(bd[0], b.x); PACKDUP(bd[1], b.y);
            PACKDUP(bd[2], b.z); PACKDUP(bd[3], b.w);
#pragma unroll
            for (int ip = 0; ip < 8; ip++)
#pragma unroll
                for (int j = 0; j < 4; j++)
                    FMA2(acc[ip][j], av[ip], bd[j]);
        }
        __syncthreads();
    }

    // epilogue: LN per row (exact k2 layout + reduction tree), then store.
    // warp row m = m0 + ty*16 + 2*ip + e; lane tx holds cols 4tx..4tx+3.
    float4 g4 = *(const float4*)(gamma + tx * 4);
    float4 b4 = *(const float4*)(beta + tx * 4);

#pragma unroll
    for (int ip = 0; ip < 8; ip++) {
#pragma unroll
        for (int e = 0; e < 2; e++) {
            int row = ty * 16 + 2 * ip + e;
            float4 v;
            {
                unsigned lo, hi;
                UNPACK2(lo, hi, acc[ip][0]); v.x = __uint_as_float(e ? hi : lo);
                UNPACK2(lo, hi, acc[ip][1]); v.y = __uint_as_float(e ? hi : lo);
                UNPACK2(lo, hi, acc[ip][2]); v.z = __uint_as_float(e ? hi : lo);
                UNPACK2(lo, hi, acc[ip][3]); v.w = __uint_as_float(e ? hi : lo);
            }
            float s = v.x + v.y + v.z + v.w;
#pragma unroll
            for (int o = 16; o; o >>= 1) s += __shfl_xor_sync(0xffffffffu, s, o);
            float mu = s * (1.0f / 128.0f);

            float dx = v.x - mu, dy = v.y - mu, dz = v.z - mu, dw = v.w - mu;
            float ss = dx * dx + dy * dy + dz * dz + dw * dw;
#pragma unroll
            for (int o = 16; o; o >>= 1) ss += __shfl_xor_sync(0xffffffffu, ss, o);
            float inv = rsqrtf(ss * (1.0f / 128.0f) + 1e-5f);

            v.x = dx * inv * g4.x + b4.x;
            v.y = dy * inv * g4.y + b4.y;
            v.z = dz * inv * g4.z + b4.z;
            v.w = dw * inv * g4.w + b4.w;
            float* dst = g_q + (size_t)(m0 + row) * QDV + n0 + tx * 4;
            *(float4*)dst = v;
        }
    }
}

// ---------------------------------------------------------------------------
// K3 (fused K4): VERBATIM round 13 (541.2us best). p-sequential dots
// (FFMA2, bit-exact k-order), selection ILP-4, pruned stage-2, softmax.
// ---------------------------------------------------------------------------
__global__ __launch_bounds__(256, 3) void k3_fused(const float* __restrict__ keys)
{
    __shared__ float qs[32][33];   // [token][k]
    __shared__ float ks[32][256];  // [k][key] transposed

    const int tid = threadIdx.x;
    const int tx = tid & 31;
    const int wy = tid >> 5;       // warp id: token group
    const int tt = blockIdx.x;
    const int h = blockIdx.y;
    const int t0 = tt * 32;

    const int tl = tid >> 3;
    const int kc = (tid & 7) << 2;

    float s1s0[4], s1s1[4];        // stage-1 results per token per p
    int   s1i0[4], s1i1[4];

#pragma unroll 1
    for (int p = 0; p < 2; p++) {
        ull acc[4][4];             // [token][key-pair-quad] — reused across p
#pragma unroll
        for (int i = 0; i < 4; i++)
#pragma unroll
            for (int jq = 0; jq < 4; jq++) acc[i][jq] = 0ULL;

        const float* qb = g_q + (size_t)(p * HV + h) * DHV;
        const float* kb = keys + ((size_t)(h * NKV + tid) * 2 + p) * DHV;
        for (int kt = 0; kt < DHV; kt += 32) {
            __syncthreads();
            float4 q4 = *(const float4*)(qb + (size_t)(t0 + tl) * QDV + kt + kc);
            qs[tl][kc + 0] = q4.x; qs[tl][kc + 1] = q4.y;
            qs[tl][kc + 2] = q4.z; qs[tl][kc + 3] = q4.w;
            const float* kr = kb + kt;  // key row n = tid (256 keys)
#pragma unroll
            for (int c = 0; c < 8; c++) {
                float4 k4 = *(const float4*)(kr + c * 4);
                ks[c * 4 + 0][tid] = k4.x; ks[c * 4 + 1][tid] = k4.y;
                ks[c * 4 + 2][tid] = k4.z; ks[c * 4 + 3][tid] = k4.w;
            }
            __syncthreads();
#pragma unroll 4
            for (int k = 0; k < 32; k++) {
                ull kv[4];
#pragma unroll
                for (int jq = 0; jq < 4; jq++)
                    kv[jq] = *(const ull*)&ks[k][64 * jq + 2 * tx];
#pragma unroll
                for (int i = 0; i < 4; i++) {
                    ull qd;
                    PACKDUP(qd, qs[wy + 8 * i][k]);
#pragma unroll
                    for (int jq = 0; jq < 4; jq++)
                        FMA2(acc[i][jq], qd, kv[jq]);
                }
            }
        }

        // stage-1 for this p: top-16 of 256 per token, ALL 4 tokens ILP.
        float v[4][8];
#pragma unroll
        for (int i = 0; i < 4; i++)
#pragma unroll
            for (int jq = 0; jq < 4; jq++) {
                unsigned lo, hi;
                UNPACK2(lo, hi, acc[i][jq]);
                v[i][2 * jq + 0] = __uint_as_float(lo);
                v[i][2 * jq + 1] = __uint_as_float(hi);
            }
        float osr[4]; int oir[4];
#pragma unroll
        for (int i = 0; i < 4; i++) { osr[i] = 0.f; oir[i] = 0; }
#pragma unroll 1
        for (int it = 0; it < 16; it++) {
            float bv[4]; int bi[4];
#pragma unroll
            for (int i = 0; i < 4; i++) { bv[i] = -INFINITY; bi[i] = 0x7fffffff; }
#pragma unroll
            for (int s = 0; s < 8; s++) {
                int n = ((s >> 1) << 6) + 2 * tx + (s & 1);
#pragma unroll
                for (int i = 0; i < 4; i++)
                    if (v[i][s] > bv[i]) { bv[i] = v[i][s]; bi[i] = n; }
            }
#pragma unroll
            for (int o = 16; o; o >>= 1) {
#pragma unroll
                for (int i = 0; i < 4; i++) {
                    float ov = __shfl_xor_sync(0xffffffffu, bv[i], o);
                    int   on = __shfl_xor_sync(0xffffffffu, bi[i], o);
                    if (ov > bv[i] || (ov == bv[i] && on < bi[i])) { bv[i] = ov; bi[i] = on; }
                }
            }
#pragma unroll
            for (int i = 0; i < 4; i++) {
                if (tx == it) { osr[i] = bv[i]; oir[i] = bi[i]; }
                if (((bi[i] >> 1) & 31) == tx) {
                    int sl = ((bi[i] >> 6) << 1) | (bi[i] & 1);
                    v[i][sl] = -INFINITY;
                }
            }
        }
#pragma unroll
        for (int i = 0; i < 4; i++) {
            if (p == 0) { s1s0[i] = osr[i]; s1i0[i] = oir[i]; }
            else        { s1s1[i] = osr[i]; s1i1[i] = oir[i]; }
        }
    }

    // stage-2: top-16 of 50 pruned candidates, ALL 4 tokens ILP.
    float v2[4][2];
    int cc2[2];                    // candidate ids identical for all tokens
#pragma unroll
    for (int e = 0; e < 2; e++) {
        int c = tx + 32 * e;
        int ii = c_ci2[c], jj = c_cj2[c];
        cc2[e] = ii * 16 + jj;
#pragma unroll
        for (int i = 0; i < 4; i++) {
            float sxv = __shfl_sync(0xffffffffu, s1s0[i], ii);
            float syv = __shfl_sync(0xffffffffu, s1s1[i], jj);
            v2[i][e] = (c < 50) ? sxv + syv : -INFINITY;
        }
    }
    float os[4]; int occ[4];
#pragma unroll
    for (int i = 0; i < 4; i++) { os[i] = 0.f; occ[i] = 0; }
#pragma unroll 1
    for (int it = 0; it < 16; it++) {
        float bv[4]; int bcc[4];
#pragma unroll
        for (int i = 0; i < 4; i++) { bv[i] = -INFINITY; bcc[i] = 0x7fffffff; }
#pragma unroll
        for (int e = 0; e < 2; e++)
#pragma unroll
            for (int i = 0; i < 4; i++)
                if (v2[i][e] > bv[i] || (v2[i][e] == bv[i] && cc2[e] < bcc[i])) {
                    bv[i] = v2[i][e]; bcc[i] = cc2[e];
                }
#pragma unroll
        for (int o = 16; o; o >>= 1) {
#pragma unroll
            for (int i = 0; i < 4; i++) {
                float ov = __shfl_xor_sync(0xffffffffu, bv[i], o);
                int   oc = __shfl_xor_sync(0xffffffffu, bcc[i], o);
                if (ov > bv[i] || (ov == bv[i] && oc < bcc[i])) { bv[i] = ov; bcc[i] = oc; }
            }
        }
#pragma unroll
        for (int i = 0; i < 4; i++) {
            if (tx == it) { os[i] = bv[i]; occ[i] = bcc[i]; }
#pragma unroll
            for (int e = 0; e < 2; e++)
                if (cc2[e] == bcc[i]) v2[i][e] = -INFINITY;
        }
    }

    // softmax over 16 selected (lane 0 = max) + index gather, ILP-4.
    float ev[4], sum[4];
#pragma unroll
    for (int i = 0; i < 4; i++) {
        float mx = __shfl_sync(0xffffffffu, os[i], 0);
        ev[i] = (tx < 16) ? expf(os[i] - mx) : 0.f;
        sum[i] = ev[i];
    }
#pragma unroll
    for (int o = 16; o; o >>= 1)
#pragma unroll
        for (int i = 0; i < 4; i++)
            sum[i] += __shfl_xor_sync(0xffffffffu, sum[i], o);
#pragma unroll
    for (int i = 0; i < 4; i++) {
        int ix = __shfl_sync(0xffffffffu, s1i0[i], (occ[i] >> 4) & 15);
        int iy = __shfl_sync(0xffffffffu, s1i1[i], occ[i] & 15);
        if (tx < 16) {
            const int t = t0 + wy + 8 * i;
            int o = (t * HV + h) * KKV + tx;
            g_attn[o] = ev[i] / sum[i];
            g_vidx[o] = ix * NKV + iy;
        }
    }
}

// ---------------------------------------------------------------------------
// K5: out[t,:] = sum_{m<128} attn[t,m] * values[vidx[t,m], :]
// (at DRAM/L2 bandwidth floor per ncu — unchanged)
// ---------------------------------------------------------------------------
__global__ __launch_bounds__(128) void k5_out(const float* __restrict__ values,
                                              float* __restrict__ out)
{
    __shared__ float sa[128];
    __shared__ int   sv[128];
    const int t = blockIdx.x;
    const int tid = threadIdx.x;
    sa[tid] = g_attn[(size_t)t * 128 + tid];
    sv[tid] = g_vidx[(size_t)t * 128 + tid];
    __syncthreads();

    const float4* V = (const float4*)values;
    float4 acc = make_float4(0.f, 0.f, 0.f, 0.f);
#pragma unroll 8
    for (int m = 0; m < 128; m++) {
        float a = sa[m];
        float4 vv = V[(size_t)sv[m] * 128 + tid];
        acc.x = fmaf(a, vv.x, acc.x);
        acc.y = fmaf(a, vv.y, acc.y);
        acc.z = fmaf(a, vv.z, acc.z);
        acc.w = fmaf(a, vv.w, acc.w);
    }
    ((float4*)out)[(size_t)t * 128 + tid] = acc;
}

// ---------------------------------------------------------------------------
extern "C" void kernel_launch(void* const* d_in, const int* in_sizes, int n_in,
                              void* d_out, int out_size)
{
    const float* x      = (const float*)d_in[0];  // (4,1024,512)
    const float* Wq     = (const float*)d_in[1];  // (2048,512)
    const float* ln_g   = (const float*)d_in[2];  // (128,)
    const float* ln_b   = (const float*)d_in[3];  // (128,)
    const float* keys   = (const float*)d_in[4];  // (8,256,2,128)
    const float* values = (const float*)d_in[5];  // (65536,512)
    float* out = (float*)d_out;                   // (4,1024,512)

    k1_gemm_ln<<<dim3(NTOKS / 128, QDV / 128), 256>>>(x, Wq, ln_g, ln_b);
    k3_fused<<<dim3(NTOKS / 32, HV), 256>>>(keys);
    k5_out<<<NTOKS, 128>>>(values, out);
}